// round 2
// baseline (speedup 1.0000x reference)
#include <cuda_runtime.h>
#include <math.h>

#define B_   2
#define S_   2048
#define D_   1024
#define H_   16
#define HD_  64
#define M_TOT (B_ * S_)   // 4096

// ---------------- scratch (no allocs allowed) ----------------
__device__ float g_q[(size_t)B_ * H_ * S_ * HD_];     // [B,H,S,HD]
__device__ float g_k[(size_t)B_ * H_ * S_ * HD_];
__device__ float g_v[(size_t)B_ * H_ * S_ * HD_];
__device__ float g_attn[(size_t)B_ * S_ * D_];        // [B,S,D] (heads concatenated)

// ==================== GEMM tiling ====================
#define BM 128
#define BN 128
#define BK 8
#define TM 8
#define TN 8
// 256 threads, each computes an 8x8 micro-tile of a 128x128 block tile.
// Software-pipelined: next A/B fragments prefetched into registers during FMA.

// ---------------- fused QKV projection ----------------
// q[b,h,s,k] = sum_d X[b,s,d] * W[h,d,k] + bias[h,k]
// GEMM view: [M_TOT, D] @ [D, H*HD], W addressed per-head.
__global__ __launch_bounds__(256) void qkv_gemm(
    const float* __restrict__ xq, const float* __restrict__ xk, const float* __restrict__ xv,
    const float* __restrict__ wq, const float* __restrict__ bq,
    const float* __restrict__ wk, const float* __restrict__ bk,
    const float* __restrict__ wv, const float* __restrict__ bv)
{
    const float* X; const float* W; const float* bias; float* out;
    if (blockIdx.z == 0)      { X = xq; W = wq; bias = bq; out = g_q; }
    else if (blockIdx.z == 1) { X = xk; W = wk; bias = bk; out = g_k; }
    else                      { X = xv; W = wv; bias = bv; out = g_v; }

    __shared__ float As[BK][BM];
    __shared__ float Bs[BK][BN];

    const int n0 = blockIdx.x * BN;
    const int m0 = blockIdx.y * BM;
    const int tid = threadIdx.x;
    const int tx = tid & 15;
    const int ty = tid >> 4;

    const int arow = tid >> 1;         // 0..127
    const int acol = (tid & 1) * 4;    // 0 or 4
    const int brow = tid >> 5;         // 0..7
    const int bcol = (tid & 31) * 4;   // 0..124 (never crosses a 64-wide head)

    const int bh  = (n0 + bcol) >> 6;  // head for B-tile load
    const int bhd = (n0 + bcol) & 63;

    float acc[TM][TN];
    #pragma unroll
    for (int i = 0; i < TM; i++)
        #pragma unroll
        for (int j = 0; j < TN; j++) acc[i][j] = 0.f;

    // prologue prefetch (k0 = 0)
    float4 a_pf = *reinterpret_cast<const float4*>(&X[(size_t)(m0 + arow) * D_ + acol]);
    float4 b_pf = *reinterpret_cast<const float4*>(&W[((size_t)bh * D_ + brow) * HD_ + bhd]);

    for (int k0 = 0; k0 < D_; k0 += BK) {
        As[acol + 0][arow] = a_pf.x;
        As[acol + 1][arow] = a_pf.y;
        As[acol + 2][arow] = a_pf.z;
        As[acol + 3][arow] = a_pf.w;
        *reinterpret_cast<float4*>(&Bs[brow][bcol]) = b_pf;
        __syncthreads();

        // prefetch next tile while FMAs below run
        if (k0 + BK < D_) {
            a_pf = *reinterpret_cast<const float4*>(
                &X[(size_t)(m0 + arow) * D_ + (k0 + BK) + acol]);
            b_pf = *reinterpret_cast<const float4*>(
                &W[((size_t)bh * D_ + (k0 + BK + brow)) * HD_ + bhd]);
        }

        #pragma unroll
        for (int k = 0; k < BK; k++) {
            float a[TM], b[TN];
            #pragma unroll
            for (int i = 0; i < TM; i += 4) {
                float4 t = *reinterpret_cast<const float4*>(&As[k][ty * TM + i]);
                a[i] = t.x; a[i+1] = t.y; a[i+2] = t.z; a[i+3] = t.w;
            }
            #pragma unroll
            for (int j = 0; j < TN; j += 4) {
                float4 t = *reinterpret_cast<const float4*>(&Bs[k][tx * TN + j]);
                b[j] = t.x; b[j+1] = t.y; b[j+2] = t.z; b[j+3] = t.w;
            }
            #pragma unroll
            for (int i = 0; i < TM; i++)
                #pragma unroll
                for (int j = 0; j < TN; j++)
                    acc[i][j] = fmaf(a[i], b[j], acc[i][j]);
        }
        __syncthreads();
    }

    // epilogue: bias add + scatter to [B,H,S,HD]
    #pragma unroll
    for (int i = 0; i < TM; i++) {
        int m = m0 + ty * TM + i;
        int bidx = m >> 11;       // / S_
        int s = m & (S_ - 1);
        #pragma unroll
        for (int j = 0; j < TN; j += 4) {
            int n = n0 + tx * TN + j;
            int h = n >> 6, hd = n & 63;
            float4 bb = *reinterpret_cast<const float4*>(&bias[h * HD_ + hd]);
            float4 o;
            o.x = acc[i][j + 0] + bb.x;
            o.y = acc[i][j + 1] + bb.y;
            o.z = acc[i][j + 2] + bb.z;
            o.w = acc[i][j + 3] + bb.w;
            *reinterpret_cast<float4*>(
                &out[(((size_t)bidx * H_ + h) * S_ + s) * HD_ + hd]) = o;
        }
    }
}

// ---------------- output projection ----------------
// Y[m,n] = sum_d g_attn[m,d] * Wo[d,n] + bo[n]
__global__ __launch_bounds__(256) void out_gemm(
    const float* __restrict__ Wo, const float* __restrict__ bo, float* __restrict__ Y)
{
    __shared__ float As[BK][BM];
    __shared__ float Bs[BK][BN];

    const int n0 = blockIdx.x * BN;
    const int m0 = blockIdx.y * BM;
    const int tid = threadIdx.x;
    const int tx = tid & 15;
    const int ty = tid >> 4;

    const int arow = tid >> 1;
    const int acol = (tid & 1) * 4;
    const int brow = tid >> 5;
    const int bcol = (tid & 31) * 4;

    float acc[TM][TN];
    #pragma unroll
    for (int i = 0; i < TM; i++)
        #pragma unroll
        for (int j = 0; j < TN; j++) acc[i][j] = 0.f;

    float4 a_pf = *reinterpret_cast<const float4*>(&g_attn[(size_t)(m0 + arow) * D_ + acol]);
    float4 b_pf = *reinterpret_cast<const float4*>(&Wo[(size_t)brow * D_ + n0 + bcol]);

    for (int k0 = 0; k0 < D_; k0 += BK) {
        As[acol + 0][arow] = a_pf.x;
        As[acol + 1][arow] = a_pf.y;
        As[acol + 2][arow] = a_pf.z;
        As[acol + 3][arow] = a_pf.w;
        *reinterpret_cast<float4*>(&Bs[brow][bcol]) = b_pf;
        __syncthreads();

        if (k0 + BK < D_) {
            a_pf = *reinterpret_cast<const float4*>(
                &g_attn[(size_t)(m0 + arow) * D_ + (k0 + BK) + acol]);
            b_pf = *reinterpret_cast<const float4*>(
                &Wo[(size_t)(k0 + BK + brow) * D_ + n0 + bcol]);
        }

        #pragma unroll
        for (int k = 0; k < BK; k++) {
            float a[TM], b[TN];
            #pragma unroll
            for (int i = 0; i < TM; i += 4) {
                float4 t = *reinterpret_cast<const float4*>(&As[k][ty * TM + i]);
                a[i] = t.x; a[i+1] = t.y; a[i+2] = t.z; a[i+3] = t.w;
            }
            #pragma unroll
            for (int j = 0; j < TN; j += 4) {
                float4 t = *reinterpret_cast<const float4*>(&Bs[k][tx * TN + j]);
                b[j] = t.x; b[j+1] = t.y; b[j+2] = t.z; b[j+3] = t.w;
            }
            #pragma unroll
            for (int i = 0; i < TM; i++)
                #pragma unroll
                for (int j = 0; j < TN; j++)
                    acc[i][j] = fmaf(a[i], b[j], acc[i][j]);
        }
        __syncthreads();
    }

    #pragma unroll
    for (int i = 0; i < TM; i++) {
        int m = m0 + ty * TM + i;
        #pragma unroll
        for (int j = 0; j < TN; j += 4) {
            int n = n0 + tx * TN + j;
            float4 bb = *reinterpret_cast<const float4*>(&bo[n]);
            float4 o;
            o.x = acc[i][j + 0] + bb.x;
            o.y = acc[i][j + 1] + bb.y;
            o.z = acc[i][j + 2] + bb.z;
            o.w = acc[i][j + 3] + bb.w;
            *reinterpret_cast<float4*>(&Y[(size_t)m * D_ + n]) = o;
        }
    }
}

// ---------------- causal flash attention (fp32) ----------------
// Block: 64 query rows, 128 threads. Thread pair (tid, tid^1) shares one query
// row; each owns 32 of the 64 head dims. Scores via shuffle-pair reduce.
#define AT_BM 64
#define AT_BN 32

__global__ __launch_bounds__(128) void attn_kernel()
{
    const int qb = blockIdx.x;
    const int h  = blockIdx.y;
    const int b  = blockIdx.z;
    const int tid = threadIdx.x;
    const int row = tid >> 1;
    const int half = tid & 1;
    const int qg = qb * AT_BM + row;            // global query index

    __shared__ float Ks[AT_BN][HD_];
    __shared__ float Vs[AT_BN][HD_];

    // load this thread's half of the query row into registers
    const float* qptr = &g_q[(((size_t)b * H_ + h) * S_ + qg) * HD_ + half * 32];
    float qf[32];
    #pragma unroll
    for (int i = 0; i < 32; i += 4) {
        float4 t = *reinterpret_cast<const float4*>(qptr + i);
        qf[i] = t.x; qf[i+1] = t.y; qf[i+2] = t.z; qf[i+3] = t.w;
    }

    float acc[32];
    #pragma unroll
    for (int i = 0; i < 32; i++) acc[i] = 0.f;
    float m_i = -INFINITY, l_i = 0.f;
    const float scale = 0.125f;   // 1/sqrt(64)

    const float* kbase = &g_k[(((size_t)b * H_ + h) * S_) * HD_];
    const float* vbase = &g_v[(((size_t)b * H_ + h) * S_) * HD_];

    const int kend = qb * AT_BM + AT_BM;  // causal: no keys beyond last query of block

    for (int kb = 0; kb < kend; kb += AT_BN) {
        __syncthreads();   // previous tile fully consumed
        // cooperative load of K,V tile: 32x64 floats each, 4 float4 per thread
        #pragma unroll
        for (int it = 0; it < 4; it++) {
            int idx = tid + it * 128;     // 0..511
            int r = idx >> 4;
            int c = (idx & 15) * 4;
            *reinterpret_cast<float4*>(&Ks[r][c]) =
                *reinterpret_cast<const float4*>(&kbase[(size_t)(kb + r) * HD_ + c]);
            *reinterpret_cast<float4*>(&Vs[r][c]) =
                *reinterpret_cast<const float4*>(&vbase[(size_t)(kb + r) * HD_ + c]);
        }
        __syncthreads();

        // scores for 32 keys (pair-reduced over the two 32-dim halves)
        float p[AT_BN];
        float mloc = m_i;
        #pragma unroll
        for (int j = 0; j < AT_BN; j++) {
            float s = 0.f;
            const float* kr = &Ks[j][half * 32];
            #pragma unroll
            for (int d = 0; d < 32; d++) s = fmaf(qf[d], kr[d], s);
            s += __shfl_xor_sync(0xffffffffu, s, 1);   // full-row dot product
            s *= scale;
            if (kb + j > qg) s = -INFINITY;            // causal mask
            p[j] = s;
            mloc = fmaxf(mloc, s);
        }

        // online softmax rescale (first tile always contains key 0 <= qg, so
        // mloc is finite from the first tile on; no NaN from inf-inf)
        float corr = __expf(m_i - mloc);
        l_i *= corr;
        #pragma unroll
        for (int d = 0; d < 32; d++) acc[d] *= corr;

        #pragma unroll
        for (int j = 0; j < AT_BN; j++) {
            float pj = __expf(p[j] - mloc);
            l_i += pj;
            const float* vr = &Vs[j][half * 32];
            #pragma unroll
            for (int d = 0; d < 32; d++) acc[d] = fmaf(pj, vr[d], acc[d]);
        }
        m_i = mloc;
    }

    const float inv = 1.f / l_i;
    float* optr = &g_attn[((size_t)b * S_ + qg) * D_ + h * HD_ + half * 32];
    #pragma unroll
    for (int i = 0; i < 32; i += 4) {
        float4 o;
        o.x = acc[i]   * inv;
        o.y = acc[i+1] * inv;
        o.z = acc[i+2] * inv;
        o.w = acc[i+3] * inv;
        *reinterpret_cast<float4*>(optr + i) = o;
    }
}

// ---------------- launch ----------------
extern "C" void kernel_launch(void* const* d_in, const int* in_sizes, int n_in,
                              void* d_out, int out_size)
{
    const float* xq = (const float*)d_in[0];
    const float* xk = (const float*)d_in[1];
    const float* xv = (const float*)d_in[2];
    // d_in[3] is the (ignored) mask
    const float* Wq = (const float*)d_in[4];
    const float* bq = (const float*)d_in[5];
    const float* Wk = (const float*)d_in[6];
    const float* bk = (const float*)d_in[7];
    const float* Wv = (const float*)d_in[8];
    const float* bv = (const float*)d_in[9];
    const float* Wo = (const float*)d_in[10];
    const float* bo = (const float*)d_in[11];
    float* out = (float*)d_out;

    dim3 g1(D_ / BN, M_TOT / BM, 3);
    qkv_gemm<<<g1, 256>>>(xq, xk, xv, Wq, bq, Wk, bk, Wv, bv);

    dim3 g2(S_ / AT_BM, H_, B_);
    attn_kernel<<<g2, 128>>>();

    dim3 g3(D_ / BN, M_TOT / BM);
    out_gemm<<<g3, 256>>>(Wo, bo, out);
}

// round 3
// speedup vs baseline: 1.0370x; 1.0370x over previous
#include <cuda_runtime.h>
#include <math.h>

#define B_   2
#define S_   2048
#define D_   1024
#define H_   16
#define HD_  64
#define M_TOT (B_ * S_)   // 4096

// ---------------- scratch (no allocs allowed) ----------------
__device__ float g_q[(size_t)B_ * H_ * S_ * HD_];     // [B,H,S,HD]
__device__ float g_k[(size_t)B_ * H_ * S_ * HD_];
__device__ float g_v[(size_t)B_ * H_ * S_ * HD_];
__device__ float g_attn[(size_t)B_ * S_ * D_];        // [B,S,D] (heads concatenated)

// ==================== GEMM tiling ====================
#define BM 128
#define BN 128
#define BK 8
#define TM 8
#define TN 8
// 256 threads, 8x8 micro-tile each. __launch_bounds__(256,2) caps regs at 128
// so TWO CTAs fit per SM (R2 profile: regs=129 -> 1 CTA/SM, fma only 47%).

// ---------------- fused QKV projection ----------------
__global__ __launch_bounds__(256, 2) void qkv_gemm(
    const float* __restrict__ xq, const float* __restrict__ xk, const float* __restrict__ xv,
    const float* __restrict__ wq, const float* __restrict__ bq,
    const float* __restrict__ wk, const float* __restrict__ bk,
    const float* __restrict__ wv, const float* __restrict__ bv)
{
    const float* X; const float* W; const float* bias; float* out;
    if (blockIdx.z == 0)      { X = xq; W = wq; bias = bq; out = g_q; }
    else if (blockIdx.z == 1) { X = xk; W = wk; bias = bk; out = g_k; }
    else                      { X = xv; W = wv; bias = bv; out = g_v; }

    __shared__ float As[BK][BM];
    __shared__ float Bs[BK][BN];

    const int n0 = blockIdx.x * BN;
    const int m0 = blockIdx.y * BM;
    const int tid = threadIdx.x;
    const int tx = tid & 15;
    const int ty = tid >> 4;

    const int arow = tid >> 1;         // 0..127
    const int acol = (tid & 1) * 4;    // 0 or 4
    const int brow = tid >> 5;         // 0..7
    const int bcol = (tid & 31) * 4;   // 0..124 (never crosses a 64-wide head)

    const int bh  = (n0 + bcol) >> 6;  // head for B-tile load
    const int bhd = (n0 + bcol) & 63;

    float acc[TM][TN];
    #pragma unroll
    for (int i = 0; i < TM; i++)
        #pragma unroll
        for (int j = 0; j < TN; j++) acc[i][j] = 0.f;

    // prologue prefetch (k0 = 0)
    float4 a_pf = *reinterpret_cast<const float4*>(&X[(size_t)(m0 + arow) * D_ + acol]);
    float4 b_pf = *reinterpret_cast<const float4*>(&W[((size_t)bh * D_ + brow) * HD_ + bhd]);

    for (int k0 = 0; k0 < D_; k0 += BK) {
        As[acol + 0][arow] = a_pf.x;
        As[acol + 1][arow] = a_pf.y;
        As[acol + 2][arow] = a_pf.z;
        As[acol + 3][arow] = a_pf.w;
        *reinterpret_cast<float4*>(&Bs[brow][bcol]) = b_pf;
        __syncthreads();

        // prefetch next tile while FMAs below run
        if (k0 + BK < D_) {
            a_pf = *reinterpret_cast<const float4*>(
                &X[(size_t)(m0 + arow) * D_ + (k0 + BK) + acol]);
            b_pf = *reinterpret_cast<const float4*>(
                &W[((size_t)bh * D_ + (k0 + BK + brow)) * HD_ + bhd]);
        }

        #pragma unroll
        for (int k = 0; k < BK; k++) {
            float a[TM], b[TN];
            #pragma unroll
            for (int i = 0; i < TM; i += 4) {
                float4 t = *reinterpret_cast<const float4*>(&As[k][ty * TM + i]);
                a[i] = t.x; a[i+1] = t.y; a[i+2] = t.z; a[i+3] = t.w;
            }
            #pragma unroll
            for (int j = 0; j < TN; j += 4) {
                float4 t = *reinterpret_cast<const float4*>(&Bs[k][tx * TN + j]);
                b[j] = t.x; b[j+1] = t.y; b[j+2] = t.z; b[j+3] = t.w;
            }
            #pragma unroll
            for (int i = 0; i < TM; i++)
                #pragma unroll
                for (int j = 0; j < TN; j++)
                    acc[i][j] = fmaf(a[i], b[j], acc[i][j]);
        }
        __syncthreads();
    }

    // epilogue: bias add + scatter to [B,H,S,HD]
    #pragma unroll
    for (int i = 0; i < TM; i++) {
        int m = m0 + ty * TM + i;
        int bidx = m >> 11;       // / S_
        int s = m & (S_ - 1);
        #pragma unroll
        for (int j = 0; j < TN; j += 4) {
            int n = n0 + tx * TN + j;
            int h = n >> 6, hd = n & 63;
            float4 bb = *reinterpret_cast<const float4*>(&bias[h * HD_ + hd]);
            float4 o;
            o.x = acc[i][j + 0] + bb.x;
            o.y = acc[i][j + 1] + bb.y;
            o.z = acc[i][j + 2] + bb.z;
            o.w = acc[i][j + 3] + bb.w;
            *reinterpret_cast<float4*>(
                &out[(((size_t)bidx * H_ + h) * S_ + s) * HD_ + hd]) = o;
        }
    }
}

// ---------------- output projection ----------------
__global__ __launch_bounds__(256, 2) void out_gemm(
    const float* __restrict__ Wo, const float* __restrict__ bo, float* __restrict__ Y)
{
    __shared__ float As[BK][BM];
    __shared__ float Bs[BK][BN];

    const int n0 = blockIdx.x * BN;
    const int m0 = blockIdx.y * BM;
    const int tid = threadIdx.x;
    const int tx = tid & 15;
    const int ty = tid >> 4;

    const int arow = tid >> 1;
    const int acol = (tid & 1) * 4;
    const int brow = tid >> 5;
    const int bcol = (tid & 31) * 4;

    float acc[TM][TN];
    #pragma unroll
    for (int i = 0; i < TM; i++)
        #pragma unroll
        for (int j = 0; j < TN; j++) acc[i][j] = 0.f;

    float4 a_pf = *reinterpret_cast<const float4*>(&g_attn[(size_t)(m0 + arow) * D_ + acol]);
    float4 b_pf = *reinterpret_cast<const float4*>(&Wo[(size_t)brow * D_ + n0 + bcol]);

    for (int k0 = 0; k0 < D_; k0 += BK) {
        As[acol + 0][arow] = a_pf.x;
        As[acol + 1][arow] = a_pf.y;
        As[acol + 2][arow] = a_pf.z;
        As[acol + 3][arow] = a_pf.w;
        *reinterpret_cast<float4*>(&Bs[brow][bcol]) = b_pf;
        __syncthreads();

        if (k0 + BK < D_) {
            a_pf = *reinterpret_cast<const float4*>(
                &g_attn[(size_t)(m0 + arow) * D_ + (k0 + BK) + acol]);
            b_pf = *reinterpret_cast<const float4*>(
                &Wo[(size_t)(k0 + BK + brow) * D_ + n0 + bcol]);
        }

        #pragma unroll
        for (int k = 0; k < BK; k++) {
            float a[TM], b[TN];
            #pragma unroll
            for (int i = 0; i < TM; i += 4) {
                float4 t = *reinterpret_cast<const float4*>(&As[k][ty * TM + i]);
                a[i] = t.x; a[i+1] = t.y; a[i+2] = t.z; a[i+3] = t.w;
            }
            #pragma unroll
            for (int j = 0; j < TN; j += 4) {
                float4 t = *reinterpret_cast<const float4*>(&Bs[k][tx * TN + j]);
                b[j] = t.x; b[j+1] = t.y; b[j+2] = t.z; b[j+3] = t.w;
            }
            #pragma unroll
            for (int i = 0; i < TM; i++)
                #pragma unroll
                for (int j = 0; j < TN; j++)
                    acc[i][j] = fmaf(a[i], b[j], acc[i][j]);
        }
        __syncthreads();
    }

    #pragma unroll
    for (int i = 0; i < TM; i++) {
        int m = m0 + ty * TM + i;
        #pragma unroll
        for (int j = 0; j < TN; j += 4) {
            int n = n0 + tx * TN + j;
            float4 bb = *reinterpret_cast<const float4*>(&bo[n]);
            float4 o;
            o.x = acc[i][j + 0] + bb.x;
            o.y = acc[i][j + 1] + bb.y;
            o.z = acc[i][j + 2] + bb.z;
            o.w = acc[i][j + 3] + bb.w;
            *reinterpret_cast<float4*>(&Y[(size_t)m * D_ + n]) = o;
        }
    }
}

// ---------------- causal flash attention (fp32) ----------------
// Block: 64 query rows, 128 threads. Thread pair (tid, tid^1) shares one query
// row; each owns 32 of the 64 head dims. Scores via shuffle-pair reduce.
// Softmax runs in exp2 domain: qf is pre-scaled by scale*log2(e), so scores
// are already log2-probabilities and exp2f is a single MUFU.EX2.
// Block order is REVERSED so the heaviest causal blocks launch first.
#define AT_BM 64
#define AT_BN 32

__global__ __launch_bounds__(128) void attn_kernel()
{
    const int nqb = S_ / AT_BM;
    const int qb = (nqb - 1) - blockIdx.x;      // heavy blocks first
    const int h  = blockIdx.y;
    const int b  = blockIdx.z;
    const int tid = threadIdx.x;
    const int row = tid >> 1;
    const int half = tid & 1;
    const int qg = qb * AT_BM + row;            // global query index

    __shared__ float Ks[AT_BN][HD_];
    __shared__ float Vs[AT_BN][HD_];

    // load this thread's half of the query row, pre-scaled into exp2 domain
    const float qscale = 0.125f * 1.4426950408889634f;   // 1/sqrt(64) * log2(e)
    const float* qptr = &g_q[(((size_t)b * H_ + h) * S_ + qg) * HD_ + half * 32];
    float qf[32];
    #pragma unroll
    for (int i = 0; i < 32; i += 4) {
        float4 t = *reinterpret_cast<const float4*>(qptr + i);
        qf[i]   = t.x * qscale;
        qf[i+1] = t.y * qscale;
        qf[i+2] = t.z * qscale;
        qf[i+3] = t.w * qscale;
    }

    float acc[32];
    #pragma unroll
    for (int i = 0; i < 32; i++) acc[i] = 0.f;
    float m_i = -INFINITY, l_i = 0.f;

    const float* kbase = &g_k[(((size_t)b * H_ + h) * S_) * HD_];
    const float* vbase = &g_v[(((size_t)b * H_ + h) * S_) * HD_];

    const int kend = qb * AT_BM + AT_BM;  // causal: no keys beyond last query of block

    for (int kb = 0; kb < kend; kb += AT_BN) {
        __syncthreads();   // previous tile fully consumed
        // cooperative load of K,V tile: 32x64 floats each, 4 float4 per thread
        #pragma unroll
        for (int it = 0; it < 4; it++) {
            int idx = tid + it * 128;     // 0..511
            int r = idx >> 4;
            int c = (idx & 15) * 4;
            *reinterpret_cast<float4*>(&Ks[r][c]) =
                *reinterpret_cast<const float4*>(&kbase[(size_t)(kb + r) * HD_ + c]);
            *reinterpret_cast<float4*>(&Vs[r][c]) =
                *reinterpret_cast<const float4*>(&vbase[(size_t)(kb + r) * HD_ + c]);
        }
        __syncthreads();

        // log2-domain scores for 32 keys (pair-reduced over the two halves)
        float p[AT_BN];
        float mloc = m_i;
        #pragma unroll
        for (int j = 0; j < AT_BN; j++) {
            float s = 0.f;
            const float* kr = &Ks[j][half * 32];
            #pragma unroll
            for (int d = 0; d < 32; d++) s = fmaf(qf[d], kr[d], s);
            s += __shfl_xor_sync(0xffffffffu, s, 1);   // full-row dot product
            if (kb + j > qg) s = -INFINITY;            // causal mask
            p[j] = s;
            mloc = fmaxf(mloc, s);
        }

        // online softmax rescale (log2 domain; first tile always has key 0)
        float corr = exp2f(m_i - mloc);
        l_i *= corr;
        #pragma unroll
        for (int d = 0; d < 32; d++) acc[d] *= corr;

        #pragma unroll
        for (int j = 0; j < AT_BN; j++) {
            float pj = exp2f(p[j] - mloc);
            l_i += pj;
            const float* vr = &Vs[j][half * 32];
            #pragma unroll
            for (int d = 0; d < 32; d++) acc[d] = fmaf(pj, vr[d], acc[d]);
        }
        m_i = mloc;
    }

    const float inv = 1.f / l_i;
    float* optr = &g_attn[((size_t)b * S_ + qg) * D_ + h * HD_ + half * 32];
    #pragma unroll
    for (int i = 0; i < 32; i += 4) {
        float4 o;
        o.x = acc[i]   * inv;
        o.y = acc[i+1] * inv;
        o.z = acc[i+2] * inv;
        o.w = acc[i+3] * inv;
        *reinterpret_cast<float4*>(optr + i) = o;
    }
}

// ---------------- launch ----------------
extern "C" void kernel_launch(void* const* d_in, const int* in_sizes, int n_in,
                              void* d_out, int out_size)
{
    const float* xq = (const float*)d_in[0];
    const float* xk = (const float*)d_in[1];
    const float* xv = (const float*)d_in[2];
    // d_in[3] is the (ignored) mask
    const float* Wq = (const float*)d_in[4];
    const float* bq = (const float*)d_in[5];
    const float* Wk = (const float*)d_in[6];
    const float* bk = (const float*)d_in[7];
    const float* Wv = (const float*)d_in[8];
    const float* bv = (const float*)d_in[9];
    const float* Wo = (const float*)d_in[10];
    const float* bo = (const float*)d_in[11];
    float* out = (float*)d_out;

    dim3 g1(D_ / BN, M_TOT / BM, 3);
    qkv_gemm<<<g1, 256>>>(xq, xk, xv, Wq, bq, Wk, bk, Wv, bv);

    dim3 g2(S_ / AT_BM, H_, B_);
    attn_kernel<<<g2, 128>>>();

    dim3 g3(D_ / BN, M_TOT / BM);
    out_gemm<<<g3, 256>>>(Wo, bo, out);
}

// round 4
// speedup vs baseline: 1.4123x; 1.3620x over previous
#include <cuda_runtime.h>
#include <math.h>

#define B_   2
#define S_   2048
#define D_   1024
#define H_   16
#define HD_  64
#define M_TOT (B_ * S_)   // 4096

// ---------------- scratch (no allocs allowed) ----------------
__device__ float g_q[(size_t)B_ * H_ * S_ * HD_];     // [B,H,S,HD]
__device__ float g_k[(size_t)B_ * H_ * S_ * HD_];
__device__ float g_v[(size_t)B_ * H_ * S_ * HD_];
__device__ float g_attn[(size_t)B_ * S_ * D_];        // [B,S,D] (heads concatenated)

// ==================== GEMM tiling ====================
#define BM 128
#define BN 128
#define BK 8
#define TM 8
#define TN 8

// ---------------- fused QKV projection ----------------
__global__ __launch_bounds__(256, 2) void qkv_gemm(
    const float* __restrict__ xq, const float* __restrict__ xk, const float* __restrict__ xv,
    const float* __restrict__ wq, const float* __restrict__ bq,
    const float* __restrict__ wk, const float* __restrict__ bk,
    const float* __restrict__ wv, const float* __restrict__ bv)
{
    const float* X; const float* W; const float* bias; float* out;
    if (blockIdx.z == 0)      { X = xq; W = wq; bias = bq; out = g_q; }
    else if (blockIdx.z == 1) { X = xk; W = wk; bias = bk; out = g_k; }
    else                      { X = xv; W = wv; bias = bv; out = g_v; }

    __shared__ float As[BK][BM];
    __shared__ float Bs[BK][BN];

    const int n0 = blockIdx.x * BN;
    const int m0 = blockIdx.y * BM;
    const int tid = threadIdx.x;
    const int tx = tid & 15;
    const int ty = tid >> 4;

    const int arow = tid >> 1;
    const int acol = (tid & 1) * 4;
    const int brow = tid >> 5;
    const int bcol = (tid & 31) * 4;

    const int bh  = (n0 + bcol) >> 6;
    const int bhd = (n0 + bcol) & 63;

    float acc[TM][TN];
    #pragma unroll
    for (int i = 0; i < TM; i++)
        #pragma unroll
        for (int j = 0; j < TN; j++) acc[i][j] = 0.f;

    float4 a_pf = *reinterpret_cast<const float4*>(&X[(size_t)(m0 + arow) * D_ + acol]);
    float4 b_pf = *reinterpret_cast<const float4*>(&W[((size_t)bh * D_ + brow) * HD_ + bhd]);

    for (int k0 = 0; k0 < D_; k0 += BK) {
        As[acol + 0][arow] = a_pf.x;
        As[acol + 1][arow] = a_pf.y;
        As[acol + 2][arow] = a_pf.z;
        As[acol + 3][arow] = a_pf.w;
        *reinterpret_cast<float4*>(&Bs[brow][bcol]) = b_pf;
        __syncthreads();

        if (k0 + BK < D_) {
            a_pf = *reinterpret_cast<const float4*>(
                &X[(size_t)(m0 + arow) * D_ + (k0 + BK) + acol]);
            b_pf = *reinterpret_cast<const float4*>(
                &W[((size_t)bh * D_ + (k0 + BK + brow)) * HD_ + bhd]);
        }

        #pragma unroll
        for (int k = 0; k < BK; k++) {
            float a[TM], b[TN];
            #pragma unroll
            for (int i = 0; i < TM; i += 4) {
                float4 t = *reinterpret_cast<const float4*>(&As[k][ty * TM + i]);
                a[i] = t.x; a[i+1] = t.y; a[i+2] = t.z; a[i+3] = t.w;
            }
            #pragma unroll
            for (int j = 0; j < TN; j += 4) {
                float4 t = *reinterpret_cast<const float4*>(&Bs[k][tx * TN + j]);
                b[j] = t.x; b[j+1] = t.y; b[j+2] = t.z; b[j+3] = t.w;
            }
            #pragma unroll
            for (int i = 0; i < TM; i++)
                #pragma unroll
                for (int j = 0; j < TN; j++)
                    acc[i][j] = fmaf(a[i], b[j], acc[i][j]);
        }
        __syncthreads();
    }

    #pragma unroll
    for (int i = 0; i < TM; i++) {
        int m = m0 + ty * TM + i;
        int bidx = m >> 11;
        int s = m & (S_ - 1);
        #pragma unroll
        for (int j = 0; j < TN; j += 4) {
            int n = n0 + tx * TN + j;
            int h = n >> 6, hd = n & 63;
            float4 bb = *reinterpret_cast<const float4*>(&bias[h * HD_ + hd]);
            float4 o;
            o.x = acc[i][j + 0] + bb.x;
            o.y = acc[i][j + 1] + bb.y;
            o.z = acc[i][j + 2] + bb.z;
            o.w = acc[i][j + 3] + bb.w;
            *reinterpret_cast<float4*>(
                &out[(((size_t)bidx * H_ + h) * S_ + s) * HD_ + hd]) = o;
        }
    }
}

// ---------------- output projection ----------------
__global__ __launch_bounds__(256, 2) void out_gemm(
    const float* __restrict__ Wo, const float* __restrict__ bo, float* __restrict__ Y)
{
    __shared__ float As[BK][BM];
    __shared__ float Bs[BK][BN];

    const int n0 = blockIdx.x * BN;
    const int m0 = blockIdx.y * BM;
    const int tid = threadIdx.x;
    const int tx = tid & 15;
    const int ty = tid >> 4;

    const int arow = tid >> 1;
    const int acol = (tid & 1) * 4;
    const int brow = tid >> 5;
    const int bcol = (tid & 31) * 4;

    float acc[TM][TN];
    #pragma unroll
    for (int i = 0; i < TM; i++)
        #pragma unroll
        for (int j = 0; j < TN; j++) acc[i][j] = 0.f;

    float4 a_pf = *reinterpret_cast<const float4*>(&g_attn[(size_t)(m0 + arow) * D_ + acol]);
    float4 b_pf = *reinterpret_cast<const float4*>(&Wo[(size_t)brow * D_ + n0 + bcol]);

    for (int k0 = 0; k0 < D_; k0 += BK) {
        As[acol + 0][arow] = a_pf.x;
        As[acol + 1][arow] = a_pf.y;
        As[acol + 2][arow] = a_pf.z;
        As[acol + 3][arow] = a_pf.w;
        *reinterpret_cast<float4*>(&Bs[brow][bcol]) = b_pf;
        __syncthreads();

        if (k0 + BK < D_) {
            a_pf = *reinterpret_cast<const float4*>(
                &g_attn[(size_t)(m0 + arow) * D_ + (k0 + BK) + acol]);
            b_pf = *reinterpret_cast<const float4*>(
                &Wo[(size_t)(k0 + BK + brow) * D_ + n0 + bcol]);
        }

        #pragma unroll
        for (int k = 0; k < BK; k++) {
            float a[TM], b[TN];
            #pragma unroll
            for (int i = 0; i < TM; i += 4) {
                float4 t = *reinterpret_cast<const float4*>(&As[k][ty * TM + i]);
                a[i] = t.x; a[i+1] = t.y; a[i+2] = t.z; a[i+3] = t.w;
            }
            #pragma unroll
            for (int j = 0; j < TN; j += 4) {
                float4 t = *reinterpret_cast<const float4*>(&Bs[k][tx * TN + j]);
                b[j] = t.x; b[j+1] = t.y; b[j+2] = t.z; b[j+3] = t.w;
            }
            #pragma unroll
            for (int i = 0; i < TM; i++)
                #pragma unroll
                for (int j = 0; j < TN; j++)
                    acc[i][j] = fmaf(a[i], b[j], acc[i][j]);
        }
        __syncthreads();
    }

    #pragma unroll
    for (int i = 0; i < TM; i++) {
        int m = m0 + ty * TM + i;
        #pragma unroll
        for (int j = 0; j < TN; j += 4) {
            int n = n0 + tx * TN + j;
            float4 bb = *reinterpret_cast<const float4*>(&bo[n]);
            float4 o;
            o.x = acc[i][j + 0] + bb.x;
            o.y = acc[i][j + 1] + bb.y;
            o.z = acc[i][j + 2] + bb.z;
            o.w = acc[i][j + 3] + bb.w;
            *reinterpret_cast<float4*>(&Y[(size_t)m * D_ + n]) = o;
        }
    }
}

// ---------------- causal flash attention: two register-tiled GEMMs ----------------
// Block = 64 query rows, 128 threads (tx = tid&7, ty = tid>>3).
// GEMM1: S[64x32], thread owns 4x4 (rows ty*4.., keys tx*4..); Q,K transposed in smem.
// softmax: online, log2 domain, per-row stats via shfl-xor over the 8-lane tx group.
// GEMM2: O[64x64] += P x V, thread owns 4x8 (rows ty*4.., dims tx*8..); P via smem.
#define AT_BM 64
#define AT_BN 32
#define PS_STRIDE 68   // row stride in floats: 16B-aligned (68*4), bank-staggered

__global__ __launch_bounds__(128) void attn_kernel()
{
    __shared__ float Qs [HD_][AT_BM];        // [d][row], pre-scaled
    __shared__ float Kst[HD_][AT_BN];        // [d][key]
    __shared__ float Vs [AT_BN][HD_];        // [key][d]
    __shared__ float Ps [AT_BN][PS_STRIDE];  // [key][row]

    const int nqb = S_ / AT_BM;
    const int qb = (nqb - 1) - blockIdx.x;   // heavy causal blocks first
    const int h  = blockIdx.y;
    const int b  = blockIdx.z;
    const int tid = threadIdx.x;
    const int tx = tid & 7;
    const int ty = tid >> 3;
    const int qg0 = qb * AT_BM;

    const float qscale = 0.125f * 1.4426950408889634f;  // 1/sqrt(HD) * log2(e)

    const float* qbase = &g_q[(((size_t)b * H_ + h) * S_ + qg0) * HD_];
    const float* kbase = &g_k[(((size_t)b * H_ + h) * S_) * HD_];
    const float* vbase = &g_v[(((size_t)b * H_ + h) * S_) * HD_];

    // ---- load Q tile transposed + pre-scaled: Qs[d][row] ----
    {
        int row = tid & 63;
        int c0  = (tid >> 6) * 32;
        #pragma unroll
        for (int i = 0; i < 32; i += 4) {
            float4 t = *reinterpret_cast<const float4*>(&qbase[(size_t)row * HD_ + c0 + i]);
            Qs[c0 + i + 0][row] = t.x * qscale;
            Qs[c0 + i + 1][row] = t.y * qscale;
            Qs[c0 + i + 2][row] = t.z * qscale;
            Qs[c0 + i + 3][row] = t.w * qscale;
        }
    }

    float acc[4][8];
    #pragma unroll
    for (int r = 0; r < 4; r++)
        #pragma unroll
        for (int d = 0; d < 8; d++) acc[r][d] = 0.f;
    float m_i[4] = {-INFINITY, -INFINITY, -INFINITY, -INFINITY};
    float l_i[4] = {0.f, 0.f, 0.f, 0.f};

    const int ntiles = 2 * (qb + 1);
    for (int t = 0; t < ntiles; t++) {
        const int kb = t * AT_BN;
        __syncthreads();   // prior GEMM2 done before overwriting K/V/P tiles

        // ---- load K tile transposed: Kst[d][key] ----
        {
            int key = tid & 31;
            int c0  = (tid >> 5) * 16;
            #pragma unroll
            for (int i = 0; i < 16; i += 4) {
                float4 tt = *reinterpret_cast<const float4*>(
                    &kbase[(size_t)(kb + key) * HD_ + c0 + i]);
                Kst[c0 + i + 0][key] = tt.x;
                Kst[c0 + i + 1][key] = tt.y;
                Kst[c0 + i + 2][key] = tt.z;
                Kst[c0 + i + 3][key] = tt.w;
            }
        }
        // ---- load V tile natural: Vs[key][d] ----
        #pragma unroll
        for (int i = 0; i < 4; i++) {
            int idx = tid + i * 128;
            int r = idx >> 4;
            int c = (idx & 15) * 4;
            *reinterpret_cast<float4*>(&Vs[r][c]) =
                *reinterpret_cast<const float4*>(&vbase[(size_t)(kb + r) * HD_ + c]);
        }
        __syncthreads();

        // ---- GEMM1: s[4][4] over 64 dims ----
        float s[4][4];
        #pragma unroll
        for (int r = 0; r < 4; r++)
            #pragma unroll
            for (int c = 0; c < 4; c++) s[r][c] = 0.f;

        #pragma unroll 8
        for (int k = 0; k < HD_; k++) {
            float4 a  = *reinterpret_cast<const float4*>(&Qs[k][ty * 4]);
            float4 bb = *reinterpret_cast<const float4*>(&Kst[k][tx * 4]);
            float av[4] = {a.x, a.y, a.z, a.w};
            float bv[4] = {bb.x, bb.y, bb.z, bb.w};
            #pragma unroll
            for (int r = 0; r < 4; r++)
                #pragma unroll
                for (int c = 0; c < 4; c++)
                    s[r][c] = fmaf(av[r], bv[c], s[r][c]);
        }

        // ---- causal mask (only straddling tiles) ----
        if (kb + AT_BN - 1 > qg0) {
            #pragma unroll
            for (int r = 0; r < 4; r++)
                #pragma unroll
                for (int c = 0; c < 4; c++)
                    if (kb + tx * 4 + c > qg0 + ty * 4 + r) s[r][c] = -INFINITY;
        }

        // ---- online softmax (log2 domain) ----
        #pragma unroll
        for (int r = 0; r < 4; r++) {
            float mt = fmaxf(fmaxf(s[r][0], s[r][1]), fmaxf(s[r][2], s[r][3]));
            mt = fmaxf(mt, __shfl_xor_sync(0xffffffffu, mt, 1));
            mt = fmaxf(mt, __shfl_xor_sync(0xffffffffu, mt, 2));
            mt = fmaxf(mt, __shfl_xor_sync(0xffffffffu, mt, 4));
            float mnew = fmaxf(m_i[r], mt);     // finite from the first tile on
            float corr = exp2f(m_i[r] - mnew);
            float p0 = exp2f(s[r][0] - mnew);
            float p1 = exp2f(s[r][1] - mnew);
            float p2 = exp2f(s[r][2] - mnew);
            float p3 = exp2f(s[r][3] - mnew);
            s[r][0] = p0; s[r][1] = p1; s[r][2] = p2; s[r][3] = p3;
            float rs = (p0 + p1) + (p2 + p3);
            rs += __shfl_xor_sync(0xffffffffu, rs, 1);
            rs += __shfl_xor_sync(0xffffffffu, rs, 2);
            rs += __shfl_xor_sync(0xffffffffu, rs, 4);
            l_i[r] = l_i[r] * corr + rs;
            #pragma unroll
            for (int d = 0; d < 8; d++) acc[r][d] *= corr;
            m_i[r] = mnew;
        }

        // ---- stage P: Ps[key][row] ----
        #pragma unroll
        for (int c = 0; c < 4; c++)
            #pragma unroll
            for (int r = 0; r < 4; r++)
                Ps[tx * 4 + c][ty * 4 + r] = s[r][c];
        __syncthreads();

        // ---- GEMM2: acc += P x V over 32 keys ----
        #pragma unroll 4
        for (int k = 0; k < AT_BN; k++) {
            float4 a  = *reinterpret_cast<const float4*>(&Ps[k][ty * 4]);
            float4 v0 = *reinterpret_cast<const float4*>(&Vs[k][tx * 8]);
            float4 v1 = *reinterpret_cast<const float4*>(&Vs[k][tx * 8 + 4]);
            float av[4] = {a.x, a.y, a.z, a.w};
            float vv[8] = {v0.x, v0.y, v0.z, v0.w, v1.x, v1.y, v1.z, v1.w};
            #pragma unroll
            for (int r = 0; r < 4; r++)
                #pragma unroll
                for (int d = 0; d < 8; d++)
                    acc[r][d] = fmaf(av[r], vv[d], acc[r][d]);
        }
    }

    // ---- epilogue: normalize + write g_attn [B,S,D] ----
    #pragma unroll
    for (int r = 0; r < 4; r++) {
        float inv = 1.f / l_i[r];
        int row = qg0 + ty * 4 + r;
        float* optr = &g_attn[((size_t)b * S_ + row) * D_ + h * HD_ + tx * 8];
        float4 o0, o1;
        o0.x = acc[r][0] * inv; o0.y = acc[r][1] * inv;
        o0.z = acc[r][2] * inv; o0.w = acc[r][3] * inv;
        o1.x = acc[r][4] * inv; o1.y = acc[r][5] * inv;
        o1.z = acc[r][6] * inv; o1.w = acc[r][7] * inv;
        *reinterpret_cast<float4*>(optr)     = o0;
        *reinterpret_cast<float4*>(optr + 4) = o1;
    }
}

// ---------------- launch ----------------
extern "C" void kernel_launch(void* const* d_in, const int* in_sizes, int n_in,
                              void* d_out, int out_size)
{
    const float* xq = (const float*)d_in[0];
    const float* xk = (const float*)d_in[1];
    const float* xv = (const float*)d_in[2];
    // d_in[3] is the (ignored) mask
    const float* Wq = (const float*)d_in[4];
    const float* bq = (const float*)d_in[5];
    const float* Wk = (const float*)d_in[6];
    const float* bk = (const float*)d_in[7];
    const float* Wv = (const float*)d_in[8];
    const float* bv = (const float*)d_in[9];
    const float* Wo = (const float*)d_in[10];
    const float* bo = (const float*)d_in[11];
    float* out = (float*)d_out;

    dim3 g1(D_ / BN, M_TOT / BM, 3);
    qkv_gemm<<<g1, 256>>>(xq, xk, xv, Wq, bq, Wk, bk, Wv, bv);

    dim3 g2(S_ / AT_BM, H_, B_);
    attn_kernel<<<g2, 128>>>();

    dim3 g3(D_ / BN, M_TOT / BM);
    out_gemm<<<g3, 256>>>(Wo, bo, out);
}